// round 3
// baseline (speedup 1.0000x reference)
#include <cuda_runtime.h>

#define MAXN 100000
#define MAXE 1000000
#define DIM 64

// ---------------- scratch (device globals; no allocation allowed) ----------------
__device__ int   g_deg[MAXN];
__device__ float g_dinv[MAXN];
__device__ int   g_off[MAXN + 1];
__device__ int   g_cur[MAXN];
__device__ int   g_srcs[MAXE];
__device__ float g_xs[MAXN * DIM];   // dinv[i] * x[i]
__device__ float g_y[MAXN * DIM];    // aggregated features
__device__ float g_csum[DIM];
__device__ float g_csum2[DIM];
__device__ float g_scale[DIM];
__device__ float g_shift[DIM];

// ---------------- 1. init: deg = 1 (self loop), zero stats ----------------
__global__ void k_init(int n) {
    int i = blockIdx.x * blockDim.x + threadIdx.x;
    if (i < n) g_deg[i] = 1;
    if (i < DIM) { g_csum[i] = 0.f; g_csum2[i] = 0.f; }
}

// ---------------- 2. degree histogram over dst ----------------
__global__ void k_hist(const int* __restrict__ dst, int E) {
    int e = blockIdx.x * blockDim.x + threadIdx.x;
    if (e < E) atomicAdd(&g_deg[dst[e]], 1);
}

// ---------------- 3. dinv ----------------
__global__ void k_dinv(int n) {
    int i = blockIdx.x * blockDim.x + threadIdx.x;
    if (i < n) g_dinv[i] = rsqrtf((float)g_deg[i]);
}

// ---------------- 4. xs = dinv * x ----------------
__global__ void k_xs(const float* __restrict__ x, int n) {
    int i = blockIdx.x * blockDim.x + threadIdx.x;
    if (i < n * DIM) g_xs[i] = x[i] * g_dinv[i >> 6];
}

// ---------------- 5. exclusive scan of edge counts (deg-1) -> offsets ----------------
__global__ void k_scan(int n) {
    __shared__ int ss[1024];
    __shared__ int s_run;
    int tid = threadIdx.x;
    if (tid == 0) s_run = 0;
    __syncthreads();
    int nchunk = (n + 4095) / 4096;
    for (int c = 0; c < nchunk; c++) {
        int base = c * 4096 + tid * 4;
        int v0 = 0, v1 = 0, v2 = 0, v3 = 0;
        if (base + 0 < n) v0 = g_deg[base + 0] - 1;
        if (base + 1 < n) v1 = g_deg[base + 1] - 1;
        if (base + 2 < n) v2 = g_deg[base + 2] - 1;
        if (base + 3 < n) v3 = g_deg[base + 3] - 1;
        int t = v0 + v1 + v2 + v3;
        ss[tid] = t;
        __syncthreads();
        // Hillis-Steele inclusive scan over 1024 thread sums
        for (int off = 1; off < 1024; off <<= 1) {
            int val = (tid >= off) ? ss[tid - off] : 0;
            __syncthreads();
            ss[tid] += val;
            __syncthreads();
        }
        int excl = ss[tid] - t + s_run;
        if (base + 0 < n) { g_off[base + 0] = excl; g_cur[base + 0] = excl; } excl += v0;
        if (base + 1 < n) { g_off[base + 1] = excl; g_cur[base + 1] = excl; } excl += v1;
        if (base + 2 < n) { g_off[base + 2] = excl; g_cur[base + 2] = excl; } excl += v2;
        if (base + 3 < n) { g_off[base + 3] = excl; g_cur[base + 3] = excl; }
        int tot = ss[1023];
        __syncthreads();
        if (tid == 0) s_run += tot;
        __syncthreads();
    }
    if (tid == 0) g_off[n] = s_run;
}

// ---------------- 6. CSR fill ----------------
__global__ void k_fill(const int* __restrict__ src, const int* __restrict__ dst, int E) {
    int e = blockIdx.x * blockDim.x + threadIdx.x;
    if (e < E) {
        int d = dst[e];
        int p = atomicAdd(&g_cur[d], 1);
        g_srcs[p] = src[e];
    }
}

// ---------------- 7. aggregation: one warp per node, float2 per lane ----------------
__global__ void k_agg(int n) {
    int warp = (blockIdx.x * blockDim.x + threadIdx.x) >> 5;
    int lane = threadIdx.x & 31;
    if (warp >= n) return;
    const float2* xs2 = (const float2*)g_xs;
    int s0 = g_off[warp], s1 = g_off[warp + 1];
    float2 a0 = xs2[warp * 32 + lane];   // self-loop term: xs[dst] = dinv[dst]*x[dst]
    float2 a1 = make_float2(0.f, 0.f);
    int e = s0;
    for (; e + 2 <= s1; e += 2) {
        int sa = g_srcs[e], sb = g_srcs[e + 1];
        float2 va = xs2[sa * 32 + lane];
        float2 vb = xs2[sb * 32 + lane];
        a0.x += va.x; a0.y += va.y;
        a1.x += vb.x; a1.y += vb.y;
    }
    if (e < s1) {
        int sa = g_srcs[e];
        float2 va = xs2[sa * 32 + lane];
        a0.x += va.x; a0.y += va.y;
    }
    float dv = g_dinv[warp];
    float2 o;
    o.x = (a0.x + a1.x) * dv;
    o.y = (a0.y + a1.y) * dv;
    ((float2*)g_y)[warp * 32 + lane] = o;
}

// ---------------- 8. GEMM (y @ W + b), ReLU, store to out, accumulate BN stats ----------------
__global__ void __launch_bounds__(256) k_gemm(const float* __restrict__ W,
                                              const float* __restrict__ b,
                                              float* __restrict__ out, int n) {
    __shared__ float sW[64 * 64];
    __shared__ float sY[64 * 68];   // stride 68 -> conflict-free, float4-aligned
    __shared__ float sB[64];
    __shared__ float sSum[128];
    int tid = threadIdx.x;

    for (int i = tid; i < 4096; i += 256) sW[i] = W[i];
    if (tid < 64) sB[tid] = b[tid];
    if (tid < 128) sSum[tid] = 0.f;

    int row0 = blockIdx.x * 64;
    const float4* y4 = (const float4*)g_y;
    for (int i = tid; i < 64 * 16; i += 256) {
        int r = i >> 4, q = i & 15;
        int grow = row0 + r;
        float4 v = (grow < n) ? y4[grow * 16 + q] : make_float4(0.f, 0.f, 0.f, 0.f);
        ((float4*)(sY + r * 68))[q] = v;
    }
    __syncthreads();

    int r  = tid >> 2;          // 0..63 (row within tile)
    int cg = (tid & 3) << 4;    // 0,16,32,48 (col base)
    float acc[16];
#pragma unroll
    for (int j = 0; j < 16; j++) acc[j] = 0.f;
    const float* yrow = sY + r * 68;
#pragma unroll
    for (int k = 0; k < 64; k++) {
        float yk = yrow[k];
        const float4* wr = (const float4*)(sW + k * 64 + cg);
#pragma unroll
        for (int q = 0; q < 4; q++) {
            float4 w = wr[q];
            acc[q * 4 + 0] = fmaf(yk, w.x, acc[q * 4 + 0]);
            acc[q * 4 + 1] = fmaf(yk, w.y, acc[q * 4 + 1]);
            acc[q * 4 + 2] = fmaf(yk, w.z, acc[q * 4 + 2]);
            acc[q * 4 + 3] = fmaf(yk, w.w, acc[q * 4 + 3]);
        }
    }
    int grow = row0 + r;
#pragma unroll
    for (int j = 0; j < 16; j++) {
        float v = acc[j] + sB[cg + j];
        acc[j] = fmaxf(v, 0.f);
    }
    if (grow < n) {
        float4* o4 = (float4*)(out + grow * 64 + cg);
        o4[0] = make_float4(acc[0],  acc[1],  acc[2],  acc[3]);
        o4[1] = make_float4(acc[4],  acc[5],  acc[6],  acc[7]);
        o4[2] = make_float4(acc[8],  acc[9],  acc[10], acc[11]);
        o4[3] = make_float4(acc[12], acc[13], acc[14], acc[15]);
    } else {
#pragma unroll
        for (int j = 0; j < 16; j++) acc[j] = 0.f;   // don't pollute stats
    }
    // per-warp reduce over the 8 rows (lanes differing in bits 2..4)
    float sq[16];
#pragma unroll
    for (int j = 0; j < 16; j++) sq[j] = acc[j] * acc[j];
#pragma unroll
    for (int off = 4; off < 32; off <<= 1) {
#pragma unroll
        for (int j = 0; j < 16; j++) {
            acc[j] += __shfl_xor_sync(0xffffffffu, acc[j], off);
            sq[j]  += __shfl_xor_sync(0xffffffffu, sq[j],  off);
        }
    }
    if ((tid & 31) < 4) {
#pragma unroll
        for (int j = 0; j < 16; j++) {
            atomicAdd(&sSum[cg + j], acc[j]);
            atomicAdd(&sSum[64 + cg + j], sq[j]);
        }
    }
    __syncthreads();
    if (tid < 64)       atomicAdd(&g_csum[tid],       sSum[tid]);
    else if (tid < 128) atomicAdd(&g_csum2[tid - 64], sSum[tid]);
}

// ---------------- 9. BN stats -> scale/shift ----------------
__global__ void k_stats(const float* __restrict__ gamma, const float* __restrict__ beta, int n) {
    int c = threadIdx.x;
    if (c < DIM) {
        float inv_n = 1.0f / (float)n;
        float mean = g_csum[c] * inv_n;
        float var  = g_csum2[c] * inv_n - mean * mean;
        var = fmaxf(var, 0.f);
        float rstd = rsqrtf(var + 1e-5f);
        float sc = gamma[c] * rstd;
        g_scale[c] = sc;
        g_shift[c] = beta[c] - mean * sc;
    }
}

// ---------------- 10. apply BN in place on out ----------------
__global__ void k_bn(float* __restrict__ out, int n) {
    int i = blockIdx.x * blockDim.x + threadIdx.x;
    if (i < n * 16) {
        float4 v  = ((float4*)out)[i];
        int cg = i & 15;
        float4 sc = ((const float4*)g_scale)[cg];
        float4 sh = ((const float4*)g_shift)[cg];
        v.x = fmaf(v.x, sc.x, sh.x);
        v.y = fmaf(v.y, sc.y, sh.y);
        v.z = fmaf(v.z, sc.z, sh.z);
        v.w = fmaf(v.w, sc.w, sh.w);
        ((float4*)out)[i] = v;
    }
}

extern "C" void kernel_launch(void* const* d_in, const int* in_sizes, int n_in,
                              void* d_out, int out_size) {
    const float* x     = (const float*)d_in[0];
    const int*   ei    = (const int*)d_in[1];
    const float* W     = (const float*)d_in[2];
    const float* b     = (const float*)d_in[3];
    const float* gamma = (const float*)d_in[4];
    const float* beta  = (const float*)d_in[5];
    float* out = (float*)d_out;

    int N = in_sizes[0] / DIM;
    int E = in_sizes[1] / 2;
    const int* src = ei;
    const int* dst = ei + E;

    k_init<<<(N + 255) / 256, 256>>>(N);
    k_hist<<<(E + 255) / 256, 256>>>(dst, E);
    k_dinv<<<(N + 255) / 256, 256>>>(N);
    k_xs<<<(N * DIM + 255) / 256, 256>>>(x, N);
    k_scan<<<1, 1024>>>(N);
    k_fill<<<(E + 255) / 256, 256>>>(src, dst, E);
    k_agg<<<(N + 7) / 8, 256>>>(N);
    k_gemm<<<(N + 63) / 64, 256>>>(W, b, out, N);
    k_stats<<<1, 64>>>(gamma, beta, N);
    k_bn<<<(N * 16 + 255) / 256, 256>>>(out, N);
}

// round 4
// speedup vs baseline: 1.0568x; 1.0568x over previous
#include <cuda_runtime.h>

#define MAXN 100000
#define MAXE 1000000
#define DIM 64

// ---------------- scratch (device globals; no allocation allowed) ----------------
__device__ int   g_deg[MAXN];        // edge count per dst (memset to 0; actual deg = count+1)
__device__ float g_dinv[MAXN];
__device__ int   g_off[MAXN + 1];
__device__ int   g_cur[MAXN];
__device__ int   g_srcs[MAXE];
__device__ float g_xs[MAXN * DIM];   // dinv[i] * x[i]
__device__ float g_stats[2 * DIM];   // [0:64) col sums, [64:128) col sumsq

// ---------------- 1. degree histogram over dst ----------------
__global__ void k_hist(const int* __restrict__ dst, int E) {
    int e = blockIdx.x * blockDim.x + threadIdx.x;
    if (e < E) atomicAdd(&g_deg[dst[e]], 1);
}

// ---------------- 2. xs = dinv * x (float4 vectorized; also emits g_dinv) ----------
__global__ void k_xs(const float4* __restrict__ x4, int n) {
    int i = blockIdx.x * blockDim.x + threadIdx.x;
    if (i < n * 16) {
        int node = i >> 4;
        float dv = rsqrtf((float)(g_deg[node] + 1));   // +1 self loop
        float4 v = x4[i];
        v.x *= dv; v.y *= dv; v.z *= dv; v.w *= dv;
        ((float4*)g_xs)[i] = v;
        if ((i & 15) == 0) g_dinv[node] = dv;
    }
}

// ---------------- 3. exclusive scan of edge counts -> offsets (warp-shfl) --------
__global__ void k_scan(int n) {
    __shared__ int warppre[32];
    __shared__ int s_run, s_tot;
    int tid = threadIdx.x, lane = tid & 31, wid = tid >> 5;
    if (tid == 0) s_run = 0;
    __syncthreads();
    int nchunk = (n + 4095) >> 12;
    for (int c = 0; c < nchunk; c++) {
        int base = (c << 12) + tid * 4;
        int v0 = (base     < n) ? g_deg[base]     : 0;
        int v1 = (base + 1 < n) ? g_deg[base + 1] : 0;
        int v2 = (base + 2 < n) ? g_deg[base + 2] : 0;
        int v3 = (base + 3 < n) ? g_deg[base + 3] : 0;
        int t = v0 + v1 + v2 + v3;
        int s = t;
#pragma unroll
        for (int o = 1; o < 32; o <<= 1) {
            int u = __shfl_up_sync(0xffffffffu, s, o);
            if (lane >= o) s += u;
        }
        if (lane == 31) warppre[wid] = s;
        __syncthreads();
        if (wid == 0) {
            int w = warppre[lane];
            int ws = w;
#pragma unroll
            for (int o = 1; o < 32; o <<= 1) {
                int u = __shfl_up_sync(0xffffffffu, ws, o);
                if (lane >= o) ws += u;
            }
            warppre[lane] = ws - w;          // exclusive warp prefix
            if (lane == 31) s_tot = ws;      // chunk total
        }
        __syncthreads();
        int excl = s_run + warppre[wid] + (s - t);
        if (base     < n) { g_off[base]     = excl; g_cur[base]     = excl; } excl += v0;
        if (base + 1 < n) { g_off[base + 1] = excl; g_cur[base + 1] = excl; } excl += v1;
        if (base + 2 < n) { g_off[base + 2] = excl; g_cur[base + 2] = excl; } excl += v2;
        if (base + 3 < n) { g_off[base + 3] = excl; g_cur[base + 3] = excl; }
        __syncthreads();
        if (tid == 0) s_run += s_tot;
        __syncthreads();
    }
    if (tid == 0) g_off[n] = s_run;
}

// ---------------- 4. CSR fill ----------------
__global__ void k_fill(const int* __restrict__ src, const int* __restrict__ dst, int E) {
    int e = blockIdx.x * blockDim.x + threadIdx.x;
    if (e < E) {
        int d = dst[e];
        int p = atomicAdd(&g_cur[d], 1);
        g_srcs[p] = src[e];
    }
}

// ---------------- 5. fused: aggregate 64 nodes into smem, GEMM+bias+ReLU, BN stats
__global__ void __launch_bounds__(256) k_gemm(const float* __restrict__ W,
                                              const float* __restrict__ b,
                                              float* __restrict__ out, int n) {
    __shared__ float sW[64 * 64];
    __shared__ float sY[64 * 68];   // stride 68 -> conflict-free, float4-aligned
    __shared__ float sB[64];
    __shared__ float sSum[128];
    int tid = threadIdx.x, lane = tid & 31, wid = tid >> 5;

    for (int i = tid; i < 4096; i += 256) sW[i] = W[i];
    if (tid < 64) sB[tid] = b[tid];
    if (tid < 128) sSum[tid] = 0.f;

    int row0 = blockIdx.x * 64;
    const float2* xs2 = (const float2*)g_xs;

    // aggregation: each warp handles 8 tile rows, float2 per lane (64 floats/row)
    for (int rr = 0; rr < 8; rr++) {
        int r = wid * 8 + rr;
        int node = row0 + r;
        float2 o = make_float2(0.f, 0.f);
        if (node < n) {
            int s0 = g_off[node], s1 = g_off[node + 1];
            float2 a0 = xs2[node * 32 + lane];          // self-loop: dinv[dst]*x[dst]
            float2 a1 = make_float2(0.f, 0.f);
            float2 a2 = make_float2(0.f, 0.f);
            float2 a3 = make_float2(0.f, 0.f);
            int e = s0;
            for (; e + 4 <= s1; e += 4) {
                int i0 = g_srcs[e], i1 = g_srcs[e + 1], i2 = g_srcs[e + 2], i3 = g_srcs[e + 3];
                float2 v0 = xs2[i0 * 32 + lane];
                float2 v1 = xs2[i1 * 32 + lane];
                float2 v2 = xs2[i2 * 32 + lane];
                float2 v3 = xs2[i3 * 32 + lane];
                a0.x += v0.x; a0.y += v0.y;
                a1.x += v1.x; a1.y += v1.y;
                a2.x += v2.x; a2.y += v2.y;
                a3.x += v3.x; a3.y += v3.y;
            }
            for (; e < s1; e++) {
                int i0 = g_srcs[e];
                float2 v = xs2[i0 * 32 + lane];
                a0.x += v.x; a0.y += v.y;
            }
            float dv = g_dinv[node];
            o.x = (a0.x + a1.x + a2.x + a3.x) * dv;
            o.y = (a0.y + a1.y + a2.y + a3.y) * dv;
        }
        *(float2*)(sY + r * 68 + lane * 2) = o;
    }
    __syncthreads();

    int r  = tid >> 2;          // 0..63 (row within tile)
    int cg = (tid & 3) << 4;    // 0,16,32,48 (col base)
    float acc[16];
#pragma unroll
    for (int j = 0; j < 16; j++) acc[j] = 0.f;
    const float* yrow = sY + r * 68;
#pragma unroll
    for (int k = 0; k < 64; k++) {
        float yk = yrow[k];
        const float4* wr = (const float4*)(sW + k * 64 + cg);
#pragma unroll
        for (int q = 0; q < 4; q++) {
            float4 w = wr[q];
            acc[q * 4 + 0] = fmaf(yk, w.x, acc[q * 4 + 0]);
            acc[q * 4 + 1] = fmaf(yk, w.y, acc[q * 4 + 1]);
            acc[q * 4 + 2] = fmaf(yk, w.z, acc[q * 4 + 2]);
            acc[q * 4 + 3] = fmaf(yk, w.w, acc[q * 4 + 3]);
        }
    }
    int grow = row0 + r;
#pragma unroll
    for (int j = 0; j < 16; j++) {
        float v = acc[j] + sB[cg + j];
        acc[j] = fmaxf(v, 0.f);
    }
    if (grow < n) {
        float4* o4 = (float4*)(out + grow * 64 + cg);
        o4[0] = make_float4(acc[0],  acc[1],  acc[2],  acc[3]);
        o4[1] = make_float4(acc[4],  acc[5],  acc[6],  acc[7]);
        o4[2] = make_float4(acc[8],  acc[9],  acc[10], acc[11]);
        o4[3] = make_float4(acc[12], acc[13], acc[14], acc[15]);
    } else {
#pragma unroll
        for (int j = 0; j < 16; j++) acc[j] = 0.f;   // don't pollute stats
    }
    // reduce across the 8 rows held by this warp (lanes differing in bits 2..4)
    float sq[16];
#pragma unroll
    for (int j = 0; j < 16; j++) sq[j] = acc[j] * acc[j];
#pragma unroll
    for (int off = 4; off < 32; off <<= 1) {
#pragma unroll
        for (int j = 0; j < 16; j++) {
            acc[j] += __shfl_xor_sync(0xffffffffu, acc[j], off);
            sq[j]  += __shfl_xor_sync(0xffffffffu, sq[j],  off);
        }
    }
    if (lane < 4) {
#pragma unroll
        for (int j = 0; j < 16; j++) {
            atomicAdd(&sSum[cg + j],      acc[j]);
            atomicAdd(&sSum[64 + cg + j], sq[j]);
        }
    }
    __syncthreads();
    if (tid < 128) atomicAdd(&g_stats[tid], sSum[tid]);
}

// ---------------- 6. fused BN stats + apply (in place on out) ----------------
__global__ void k_bn(float4* __restrict__ out,
                     const float* __restrict__ gamma,
                     const float* __restrict__ beta, int n) {
    __shared__ float ssc[64], ssh[64];
    int tid = threadIdx.x;
    if (tid < 64) {
        float inv_n = 1.0f / (float)n;
        float mean = g_stats[tid] * inv_n;
        float var  = fmaxf(g_stats[64 + tid] * inv_n - mean * mean, 0.f);
        float sc = gamma[tid] * rsqrtf(var + 1e-5f);
        ssc[tid] = sc;
        ssh[tid] = beta[tid] - mean * sc;
    }
    __syncthreads();
    int i = blockIdx.x * blockDim.x + tid;
    if (i < n * 16) {
        float4 v  = out[i];
        float4 sc = ((const float4*)ssc)[i & 15];
        float4 sh = ((const float4*)ssh)[i & 15];
        v.x = fmaf(v.x, sc.x, sh.x);
        v.y = fmaf(v.y, sc.y, sh.y);
        v.z = fmaf(v.z, sc.z, sh.z);
        v.w = fmaf(v.w, sc.w, sh.w);
        out[i] = v;
    }
}

extern "C" void kernel_launch(void* const* d_in, const int* in_sizes, int n_in,
                              void* d_out, int out_size) {
    const float* x     = (const float*)d_in[0];
    const int*   ei    = (const int*)d_in[1];
    const float* W     = (const float*)d_in[2];
    const float* b     = (const float*)d_in[3];
    const float* gamma = (const float*)d_in[4];
    const float* beta  = (const float*)d_in[5];
    float* out = (float*)d_out;

    int N = in_sizes[0] / DIM;
    int E = in_sizes[1] / 2;
    const int* src = ei;
    const int* dst = ei + E;

    void* p_deg = nullptr;
    void* p_stats = nullptr;
    cudaGetSymbolAddress(&p_deg,   g_deg);
    cudaGetSymbolAddress(&p_stats, g_stats);
    cudaMemsetAsync(p_deg,   0, (size_t)N * sizeof(int));
    cudaMemsetAsync(p_stats, 0, 2 * DIM * sizeof(float));

    k_hist<<<(E + 255) / 256, 256>>>(dst, E);
    k_xs<<<(N * 16 + 255) / 256, 256>>>((const float4*)x, N);
    k_scan<<<1, 1024>>>(N);
    k_fill<<<(E + 255) / 256, 256>>>(src, dst, E);
    k_gemm<<<(N + 63) / 64, 256>>>(W, b, out, N);
    k_bn<<<(N * 16 + 255) / 256, 256>>>((float4*)out, gamma, beta, N);
}